// round 13
// baseline (speedup 1.0000x reference)
#include <cuda_runtime.h>

#define D_MODEL 1024
#define NH      16
#define HD      64
#define BB      4
#define TT      2048
#define NTOK    (BB * TT)      // 8192
#define BHN     (BB * NH)      // 64

// ---------------- scratch (no cudaMalloc allowed) ----------------
__device__ float g_q[(size_t)BHN * TT * HD];     // [B,H,T,hd] 32MB
__device__ float g_k[(size_t)BHN * TT * HD];
__device__ float g_v[(size_t)BHN * TT * HD];
__device__ float g_att[(size_t)NTOK * D_MODEL];  // [B,T,C]    32MB

// =================================================================
// NT SGEMM: C[m,n] = sum_k A[m,k] * W[n,k] + bias[n]
// BM=BN=128, BK=16, 256 threads, 8x8 microtile, register prefetch.
// MODE 0: A = x, scatter into g_q/g_k/g_v   (N=3072)
// MODE 1: A = g_att, write to out           (N=1024)
// =================================================================
template <int MODE>
__global__ __launch_bounds__(256)
void gemm_nt(const float* __restrict__ A_in, const float* __restrict__ W,
             const float* __restrict__ bias, float* __restrict__ out,
             int N, int K)
{
    __shared__ float As[16][132];
    __shared__ float Bs[16][132];

    const float* __restrict__ A = (MODE == 1) ? (const float*)g_att : A_in;

    const int tid = threadIdx.x;
    const int tx  = tid & 15;        // N direction (8 cols each)
    const int ty  = tid >> 4;        // M direction (8 rows each)
    const int m0  = blockIdx.y * 128;
    const int n0  = blockIdx.x * 128;

    const int lrow = tid >> 2;              // 0..63
    const int lk   = (tid & 3) << 2;        // 0,4,8,12
    const int K4   = K >> 2;

    const float4* Ag = reinterpret_cast<const float4*>(A) + (size_t)m0 * K4 + (lk >> 2);
    const float4* Wg = reinterpret_cast<const float4*>(W) + (size_t)n0 * K4 + (lk >> 2);

    float acc[8][8];
    #pragma unroll
    for (int i = 0; i < 8; i++)
        #pragma unroll
        for (int j = 0; j < 8; j++) acc[i][j] = 0.f;

    // prefetch tile 0
    float4 pa0 = Ag[(size_t)lrow * K4];
    float4 pa1 = Ag[(size_t)(lrow + 64) * K4];
    float4 pb0 = Wg[(size_t)lrow * K4];
    float4 pb1 = Wg[(size_t)(lrow + 64) * K4];

    As[lk+0][lrow]    = pa0.x; As[lk+1][lrow]    = pa0.y; As[lk+2][lrow]    = pa0.z; As[lk+3][lrow]    = pa0.w;
    As[lk+0][lrow+64] = pa1.x; As[lk+1][lrow+64] = pa1.y; As[lk+2][lrow+64] = pa1.z; As[lk+3][lrow+64] = pa1.w;
    Bs[lk+0][lrow]    = pb0.x; Bs[lk+1][lrow]    = pb0.y; Bs[lk+2][lrow]    = pb0.z; Bs[lk+3][lrow]    = pb0.w;
    Bs[lk+0][lrow+64] = pb1.x; Bs[lk+1][lrow+64] = pb1.y; Bs[lk+2][lrow+64] = pb1.z; Bs[lk+3][lrow+64] = pb1.w;
    __syncthreads();

    const int NKT = K >> 4;
    for (int kt = 0; kt < NKT; ++kt) {
        if (kt + 1 < NKT) {
            size_t off = (size_t)(kt + 1) * 4;   // 4 float4 = 16 floats
            pa0 = Ag[(size_t)lrow * K4 + off];
            pa1 = Ag[(size_t)(lrow + 64) * K4 + off];
            pb0 = Wg[(size_t)lrow * K4 + off];
            pb1 = Wg[(size_t)(lrow + 64) * K4 + off];
        }
        #pragma unroll
        for (int k = 0; k < 16; k++) {
            float4 t0 = *reinterpret_cast<const float4*>(&As[k][ty * 8]);
            float4 t1 = *reinterpret_cast<const float4*>(&As[k][ty * 8 + 4]);
            float af[8] = {t0.x, t0.y, t0.z, t0.w, t1.x, t1.y, t1.z, t1.w};
            t0 = *reinterpret_cast<const float4*>(&Bs[k][tx * 8]);
            t1 = *reinterpret_cast<const float4*>(&Bs[k][tx * 8 + 4]);
            float bf[8] = {t0.x, t0.y, t0.z, t0.w, t1.x, t1.y, t1.z, t1.w};
            #pragma unroll
            for (int i = 0; i < 8; i++)
                #pragma unroll
                for (int j = 0; j < 8; j++)
                    acc[i][j] += af[i] * bf[j];
        }
        if (kt + 1 < NKT) {
            __syncthreads();
            As[lk+0][lrow]    = pa0.x; As[lk+1][lrow]    = pa0.y; As[lk+2][lrow]    = pa0.z; As[lk+3][lrow]    = pa0.w;
            As[lk+0][lrow+64] = pa1.x; As[lk+1][lrow+64] = pa1.y; As[lk+2][lrow+64] = pa1.z; As[lk+3][lrow+64] = pa1.w;
            Bs[lk+0][lrow]    = pb0.x; Bs[lk+1][lrow]    = pb0.y; Bs[lk+2][lrow]    = pb0.z; Bs[lk+3][lrow]    = pb0.w;
            Bs[lk+0][lrow+64] = pb1.x; Bs[lk+1][lrow+64] = pb1.y; Bs[lk+2][lrow+64] = pb1.z; Bs[lk+3][lrow+64] = pb1.w;
            __syncthreads();
        }
    }

    float bv[8];
    #pragma unroll
    for (int j = 0; j < 8; j++) bv[j] = bias[n0 + tx * 8 + j];

    if (MODE == 0) {
        // scatter into g_q/g_k/g_v at [B,H,T,hd]
        const int which = n0 >> 10;   // tile never crosses a 1024 boundary
        float* __restrict__ dst = (which == 0) ? g_q : (which == 1) ? g_k : g_v;
        #pragma unroll
        for (int ii = 0; ii < 8; ii++) {
            int mi = m0 + ty * 8 + ii;
            int b  = mi >> 11;            // / TT
            int t  = mi & (TT - 1);
            #pragma unroll
            for (int jj = 0; jj < 8; jj++) {
                int r = (n0 + tx * 8 + jj) & (D_MODEL - 1);
                int h = r >> 6;
                int d = r & 63;
                dst[(((size_t)(b * NH + h) * TT + t) << 6) + d] = acc[ii][jj] + bv[jj];
            }
        }
    } else {
        #pragma unroll
        for (int ii = 0; ii < 8; ii++) {
            int mi = m0 + ty * 8 + ii;
            float4 v0 = make_float4(acc[ii][0] + bv[0], acc[ii][1] + bv[1],
                                    acc[ii][2] + bv[2], acc[ii][3] + bv[3]);
            float4 v1 = make_float4(acc[ii][4] + bv[4], acc[ii][5] + bv[5],
                                    acc[ii][6] + bv[6], acc[ii][7] + bv[7]);
            float4* po = reinterpret_cast<float4*>(out + (size_t)mi * N + n0 + tx * 8);
            po[0] = v0; po[1] = v1;
        }
    }
}

// =================================================================
// Causal flash attention, fp32. One thread = one query row.
// Block: 128 threads = 128 query rows. Grid: (T/128, B*H).
// K/V tiles of 32 keys staged in SMEM; online softmax per row.
// Writes O/l directly into g_att at [B,T,C].
// =================================================================
__global__ __launch_bounds__(128)
void attn_kernel()
{
    __shared__ float4 Ks[32][16];   // 32 keys x 64 floats
    __shared__ float4 Vs[32][16];

    const int tid = threadIdx.x;
    const int bh  = blockIdx.y;
    const int i   = blockIdx.x * 128 + tid;   // query row (== token t)

    // q row into registers, pre-scaled by 1/sqrt(hd)
    const float4* qp = reinterpret_cast<const float4*>(g_q + ((size_t)bh * TT + i) * HD);
    float4 q4[16];
    #pragma unroll
    for (int d = 0; d < 16; d++) {
        float4 v = qp[d];
        v.x *= 0.125f; v.y *= 0.125f; v.z *= 0.125f; v.w *= 0.125f;
        q4[d] = v;
    }

    float4 o4[16];
    #pragma unroll
    for (int d = 0; d < 16; d++) o4[d] = make_float4(0.f, 0.f, 0.f, 0.f);
    float mmax = -1e30f, lsum = 0.f;

    const float4* kg = reinterpret_cast<const float4*>(g_k + (size_t)bh * TT * HD);
    const float4* vg = reinterpret_cast<const float4*>(g_v + (size_t)bh * TT * HD);
    const int kend = blockIdx.x * 128 + 128;

    #pragma unroll 1
    for (int k0 = 0; k0 < kend; k0 += 32) {
        __syncthreads();
        #pragma unroll
        for (int u = 0; u < 4; u++) {
            int idx = tid + u * 128;           // 0..511 float4s
            (&Ks[0][0])[idx] = kg[k0 * 16 + idx];
            (&Vs[0][0])[idx] = vg[k0 * 16 + idx];
        }
        __syncthreads();

        #pragma unroll 1
        for (int g = 0; g < 4; ++g) {
            const int jbase = k0 + g * 8;
            // whole warp fully masked for this group -> skip
            if (__all_sync(0xffffffffu, jbase > i)) continue;

            float s[8];
            #pragma unroll
            for (int jj = 0; jj < 8; jj++) {
                float a0 = 0.f, a1 = 0.f, a2 = 0.f, a3 = 0.f;
                #pragma unroll
                for (int d = 0; d < 16; d += 4) {
                    float4 kk;
                    kk = Ks[g*8+jj][d+0]; a0 += q4[d+0].x*kk.x + q4[d+0].y*kk.y + q4[d+0].z*kk.z + q4[d+0].w*kk.w;
                    kk = Ks[g*8+jj][d+1]; a1 += q4[d+1].x*kk.x + q4[d+1].y*kk.y + q4[d+1].z*kk.z + q4[d+1].w*kk.w;
                    kk = Ks[g*8+jj][d+2]; a2 += q4[d+2].x*kk.x + q4[d+2].y*kk.y + q4[d+2].z*kk.z + q4[d+2].w*kk.w;
                    kk = Ks[g*8+jj][d+3]; a3 += q4[d+3].x*kk.x + q4[d+3].y*kk.y + q4[d+3].z*kk.z + q4[d+3].w*kk.w;
                }
                float sv = (a0 + a1) + (a2 + a3);
                s[jj] = (jbase + jj <= i) ? sv : -1e30f;
            }

            float tm = mmax;
            #pragma unroll
            for (int jj = 0; jj < 8; jj++) tm = fmaxf(tm, s[jj]);
            float corr = __expf(mmax - tm);    // 0 when mmax = -1e30 (first group)
            mmax = tm;
            lsum *= corr;
            #pragma unroll
            for (int d = 0; d < 16; d++) {
                o4[d].x *= corr; o4[d].y *= corr; o4[d].z *= corr; o4[d].w *= corr;
            }
            #pragma unroll
            for (int jj = 0; jj < 8; jj++) {
                float p = __expf(s[jj] - mmax);   // underflows to 0 for masked keys
                lsum += p;
                #pragma unroll
                for (int d = 0; d < 16; d++) {
                    float4 vv = Vs[g*8+jj][d];
                    o4[d].x += p * vv.x; o4[d].y += p * vv.y;
                    o4[d].z += p * vv.z; o4[d].w += p * vv.w;
                }
            }
        }
    }

    const float inv = 1.0f / lsum;
    const int b = bh >> 4;
    const int h = bh & 15;
    float4* op = reinterpret_cast<float4*>(g_att + (size_t)(b * TT + i) * D_MODEL + h * HD);
    #pragma unroll
    for (int d = 0; d < 16; d++) {
        float4 v = o4[d];
        v.x *= inv; v.y *= inv; v.z *= inv; v.w *= inv;
        op[d] = v;
    }
}

// =================================================================
extern "C" void kernel_launch(void* const* d_in, const int* in_sizes, int n_in,
                              void* d_out, int out_size)
{
    const float* x      = (const float*)d_in[0];
    const float* qkv_w  = (const float*)d_in[1];
    const float* qkv_b  = (const float*)d_in[2];
    const float* out_w  = (const float*)d_in[3];
    const float* out_b  = (const float*)d_in[4];
    float* out = (float*)d_out;

    // 1) QKV projection: [8192,1024] x [3072,1024]^T -> scatter q/k/v
    gemm_nt<0><<<dim3(3 * D_MODEL / 128, NTOK / 128), 256>>>(x, qkv_w, qkv_b, nullptr, 3 * D_MODEL, D_MODEL);

    // 2) causal flash attention -> g_att [B,T,C]
    attn_kernel<<<dim3(TT / 128, BHN), 128>>>();

    // 3) output projection: [8192,1024] x [1024,1024]^T + bias -> out
    gemm_nt<1><<<dim3(D_MODEL / 128, NTOK / 128), 256>>>(nullptr, out_w, out_b, out, D_MODEL, D_MODEL);
}

// round 14
// speedup vs baseline: 1.0133x; 1.0133x over previous
#include <cuda_runtime.h>

#define D_MODEL 1024
#define NH      16
#define HD      64
#define BB      4
#define TT      2048
#define NTOK    (BB * TT)      // 8192
#define BHN     (BB * NH)      // 64

// ---------------- scratch (no cudaMalloc allowed) ----------------
__device__ float g_q[(size_t)BHN * TT * HD];     // [B,H,T,hd] 32MB
__device__ float g_k[(size_t)BHN * TT * HD];
__device__ float g_v[(size_t)BHN * TT * HD];
__device__ float g_att[(size_t)NTOK * D_MODEL];  // [B,T,C]    32MB

// =================================================================
// NT SGEMM: C[m,n] = sum_k A[m,k] * W[n,k] + bias[n]
// BM=BN=128, BK=16, 256 threads, 8x8 microtile, register prefetch.
// MODE 0: A = x, scatter into g_q/g_k/g_v   (N=3072)
// MODE 1: A = g_att, write to out           (N=1024)
// =================================================================
template <int MODE>
__global__ __launch_bounds__(256)
void gemm_nt(const float* __restrict__ A_in, const float* __restrict__ W,
             const float* __restrict__ bias, float* __restrict__ out,
             int N, int K)
{
    __shared__ float As[16][132];
    __shared__ float Bs[16][132];

    const float* __restrict__ A = (MODE == 1) ? (const float*)g_att : A_in;

    const int tid = threadIdx.x;
    const int tx  = tid & 15;        // N direction (8 cols each)
    const int ty  = tid >> 4;        // M direction (8 rows each)
    const int m0  = blockIdx.y * 128;
    const int n0  = blockIdx.x * 128;

    const int lrow = tid >> 2;              // 0..63
    const int lk   = (tid & 3) << 2;        // 0,4,8,12
    const int K4   = K >> 2;

    const float4* Ag = reinterpret_cast<const float4*>(A) + (size_t)m0 * K4 + (lk >> 2);
    const float4* Wg = reinterpret_cast<const float4*>(W) + (size_t)n0 * K4 + (lk >> 2);

    float acc[8][8];
    #pragma unroll
    for (int i = 0; i < 8; i++)
        #pragma unroll
        for (int j = 0; j < 8; j++) acc[i][j] = 0.f;

    // prefetch tile 0
    float4 pa0 = Ag[(size_t)lrow * K4];
    float4 pa1 = Ag[(size_t)(lrow + 64) * K4];
    float4 pb0 = Wg[(size_t)lrow * K4];
    float4 pb1 = Wg[(size_t)(lrow + 64) * K4];

    As[lk+0][lrow]    = pa0.x; As[lk+1][lrow]    = pa0.y; As[lk+2][lrow]    = pa0.z; As[lk+3][lrow]    = pa0.w;
    As[lk+0][lrow+64] = pa1.x; As[lk+1][lrow+64] = pa1.y; As[lk+2][lrow+64] = pa1.z; As[lk+3][lrow+64] = pa1.w;
    Bs[lk+0][lrow]    = pb0.x; Bs[lk+1][lrow]    = pb0.y; Bs[lk+2][lrow]    = pb0.z; Bs[lk+3][lrow]    = pb0.w;
    Bs[lk+0][lrow+64] = pb1.x; Bs[lk+1][lrow+64] = pb1.y; Bs[lk+2][lrow+64] = pb1.z; Bs[lk+3][lrow+64] = pb1.w;
    __syncthreads();

    const int NKT = K >> 4;
    for (int kt = 0; kt < NKT; ++kt) {
        if (kt + 1 < NKT) {
            size_t off = (size_t)(kt + 1) * 4;   // 4 float4 = 16 floats
            pa0 = Ag[(size_t)lrow * K4 + off];
            pa1 = Ag[(size_t)(lrow + 64) * K4 + off];
            pb0 = Wg[(size_t)lrow * K4 + off];
            pb1 = Wg[(size_t)(lrow + 64) * K4 + off];
        }
        #pragma unroll
        for (int k = 0; k < 16; k++) {
            float4 t0 = *reinterpret_cast<const float4*>(&As[k][ty * 8]);
            float4 t1 = *reinterpret_cast<const float4*>(&As[k][ty * 8 + 4]);
            float af[8] = {t0.x, t0.y, t0.z, t0.w, t1.x, t1.y, t1.z, t1.w};
            t0 = *reinterpret_cast<const float4*>(&Bs[k][tx * 8]);
            t1 = *reinterpret_cast<const float4*>(&Bs[k][tx * 8 + 4]);
            float bf[8] = {t0.x, t0.y, t0.z, t0.w, t1.x, t1.y, t1.z, t1.w};
            #pragma unroll
            for (int i = 0; i < 8; i++)
                #pragma unroll
                for (int j = 0; j < 8; j++)
                    acc[i][j] += af[i] * bf[j];
        }
        if (kt + 1 < NKT) {
            __syncthreads();
            As[lk+0][lrow]    = pa0.x; As[lk+1][lrow]    = pa0.y; As[lk+2][lrow]    = pa0.z; As[lk+3][lrow]    = pa0.w;
            As[lk+0][lrow+64] = pa1.x; As[lk+1][lrow+64] = pa1.y; As[lk+2][lrow+64] = pa1.z; As[lk+3][lrow+64] = pa1.w;
            Bs[lk+0][lrow]    = pb0.x; Bs[lk+1][lrow]    = pb0.y; Bs[lk+2][lrow]    = pb0.z; Bs[lk+3][lrow]    = pb0.w;
            Bs[lk+0][lrow+64] = pb1.x; Bs[lk+1][lrow+64] = pb1.y; Bs[lk+2][lrow+64] = pb1.z; Bs[lk+3][lrow+64] = pb1.w;
            __syncthreads();
        }
    }

    float bv[8];
    #pragma unroll
    for (int j = 0; j < 8; j++) bv[j] = bias[n0 + tx * 8 + j];

    if (MODE == 0) {
        // scatter into g_q/g_k/g_v at [B,H,T,hd]
        const int which = n0 >> 10;   // tile never crosses a 1024 boundary
        float* __restrict__ dst = (which == 0) ? g_q : (which == 1) ? g_k : g_v;
        #pragma unroll
        for (int ii = 0; ii < 8; ii++) {
            int mi = m0 + ty * 8 + ii;
            int b  = mi >> 11;            // / TT
            int t  = mi & (TT - 1);
            #pragma unroll
            for (int jj = 0; jj < 8; jj++) {
                int r = (n0 + tx * 8 + jj) & (D_MODEL - 1);
                int h = r >> 6;
                int d = r & 63;
                dst[(((size_t)(b * NH + h) * TT + t) << 6) + d] = acc[ii][jj] + bv[jj];
            }
        }
    } else {
        #pragma unroll
        for (int ii = 0; ii < 8; ii++) {
            int mi = m0 + ty * 8 + ii;
            float4 v0 = make_float4(acc[ii][0] + bv[0], acc[ii][1] + bv[1],
                                    acc[ii][2] + bv[2], acc[ii][3] + bv[3]);
            float4 v1 = make_float4(acc[ii][4] + bv[4], acc[ii][5] + bv[5],
                                    acc[ii][6] + bv[6], acc[ii][7] + bv[7]);
            float4* po = reinterpret_cast<float4*>(out + (size_t)mi * N + n0 + tx * 8);
            po[0] = v0; po[1] = v1;
        }
    }
}

// =================================================================
// Causal flash attention, fp32. One thread = one query row.
// Block: 128 threads = 128 query rows. Grid: (T/128, B*H).
// K/V tiles of 32 keys staged in SMEM; online softmax per row.
// Writes O/l directly into g_att at [B,T,C].
// =================================================================
__global__ __launch_bounds__(128)
void attn_kernel()
{
    __shared__ float4 Ks[32][16];   // 32 keys x 64 floats
    __shared__ float4 Vs[32][16];

    const int tid = threadIdx.x;
    const int bh  = blockIdx.y;
    const int i   = blockIdx.x * 128 + tid;   // query row (== token t)

    // q row into registers, pre-scaled by 1/sqrt(hd)
    const float4* qp = reinterpret_cast<const float4*>(g_q + ((size_t)bh * TT + i) * HD);
    float4 q4[16];
    #pragma unroll
    for (int d = 0; d < 16; d++) {
        float4 v = qp[d];
        v.x *= 0.125f; v.y *= 0.125f; v.z *= 0.125f; v.w *= 0.125f;
        q4[d] = v;
    }

    float4 o4[16];
    #pragma unroll
    for (int d = 0; d < 16; d++) o4[d] = make_float4(0.f, 0.f, 0.f, 0.f);
    float mmax = -1e30f, lsum = 0.f;

    const float4* kg = reinterpret_cast<const float4*>(g_k + (size_t)bh * TT * HD);
    const float4* vg = reinterpret_cast<const float4*>(g_v + (size_t)bh * TT * HD);
    const int kend = blockIdx.x * 128 + 128;

    #pragma unroll 1
    for (int k0 = 0; k0 < kend; k0 += 32) {
        __syncthreads();
        #pragma unroll
        for (int u = 0; u < 4; u++) {
            int idx = tid + u * 128;           // 0..511 float4s
            (&Ks[0][0])[idx] = kg[k0 * 16 + idx];
            (&Vs[0][0])[idx] = vg[k0 * 16 + idx];
        }
        __syncthreads();

        #pragma unroll 1
        for (int g = 0; g < 4; ++g) {
            const int jbase = k0 + g * 8;
            // whole warp fully masked for this group -> skip
            if (__all_sync(0xffffffffu, jbase > i)) continue;

            float s[8];
            #pragma unroll
            for (int jj = 0; jj < 8; jj++) {
                float a0 = 0.f, a1 = 0.f, a2 = 0.f, a3 = 0.f;
                #pragma unroll
                for (int d = 0; d < 16; d += 4) {
                    float4 kk;
                    kk = Ks[g*8+jj][d+0]; a0 += q4[d+0].x*kk.x + q4[d+0].y*kk.y + q4[d+0].z*kk.z + q4[d+0].w*kk.w;
                    kk = Ks[g*8+jj][d+1]; a1 += q4[d+1].x*kk.x + q4[d+1].y*kk.y + q4[d+1].z*kk.z + q4[d+1].w*kk.w;
                    kk = Ks[g*8+jj][d+2]; a2 += q4[d+2].x*kk.x + q4[d+2].y*kk.y + q4[d+2].z*kk.z + q4[d+2].w*kk.w;
                    kk = Ks[g*8+jj][d+3]; a3 += q4[d+3].x*kk.x + q4[d+3].y*kk.y + q4[d+3].z*kk.z + q4[d+3].w*kk.w;
                }
                float sv = (a0 + a1) + (a2 + a3);
                s[jj] = (jbase + jj <= i) ? sv : -1e30f;
            }

            float tm = mmax;
            #pragma unroll
            for (int jj = 0; jj < 8; jj++) tm = fmaxf(tm, s[jj]);
            float corr = __expf(mmax - tm);    // 0 when mmax = -1e30 (first group)
            mmax = tm;
            lsum *= corr;
            #pragma unroll
            for (int d = 0; d < 16; d++) {
                o4[d].x *= corr; o4[d].y *= corr; o4[d].z *= corr; o4[d].w *= corr;
            }
            #pragma unroll
            for (int jj = 0; jj < 8; jj++) {
                float p = __expf(s[jj] - mmax);   // underflows to 0 for masked keys
                lsum += p;
                #pragma unroll
                for (int d = 0; d < 16; d++) {
                    float4 vv = Vs[g*8+jj][d];
                    o4[d].x += p * vv.x; o4[d].y += p * vv.y;
                    o4[d].z += p * vv.z; o4[d].w += p * vv.w;
                }
            }
        }
    }

    const float inv = 1.0f / lsum;
    const int b = bh >> 4;
    const int h = bh & 15;
    float4* op = reinterpret_cast<float4*>(g_att + (size_t)(b * TT + i) * D_MODEL + h * HD);
    #pragma unroll
    for (int d = 0; d < 16; d++) {
        float4 v = o4[d];
        v.x *= inv; v.y *= inv; v.z *= inv; v.w *= inv;
        op[d] = v;
    }
}

// =================================================================
extern "C" void kernel_launch(void* const* d_in, const int* in_sizes, int n_in,
                              void* d_out, int out_size)
{
    const float* x      = (const float*)d_in[0];
    const float* qkv_w  = (const float*)d_in[1];
    const float* qkv_b  = (const float*)d_in[2];
    const float* out_w  = (const float*)d_in[3];
    const float* out_b  = (const float*)d_in[4];
    float* out = (float*)d_out;

    // 1) QKV projection: [8192,1024] x [3072,1024]^T -> scatter q/k/v
    gemm_nt<0><<<dim3(3 * D_MODEL / 128, NTOK / 128), 256>>>(x, qkv_w, qkv_b, nullptr, 3 * D_MODEL, D_MODEL);

    // 2) causal flash attention -> g_att [B,T,C]
    attn_kernel<<<dim3(TT / 128, BHN), 128>>>();

    // 3) output projection: [8192,1024] x [1024,1024]^T + bias -> out
    gemm_nt<1><<<dim3(D_MODEL / 128, NTOK / 128), 256>>>(nullptr, out_w, out_b, out, D_MODEL, D_MODEL);
}